// round 2
// baseline (speedup 1.0000x reference)
#include <cuda_runtime.h>
#include <cuda_bf16.h>
#include <math.h>

#define NN 50000
#define EE 800000
#define DIM 128
#define HC 256        // HEADS*DIM
#define DMLP 512

// ---------------- scratch (device globals; no allocation) ----------------
__device__ float g_x   [NN * DIM];     // running residual stream
__device__ float g_h   [NN * DIM];     // layernorm output
__device__ float g_xl  [NN * HC];      // source transform
__device__ float g_xr  [NN * HC];      // target transform
__device__ float g_agg [NN * HC];      // attention aggregate
__device__ float g_mlp [NN * DMLP];    // MLP hidden
__device__ float g_s   [EE * 2];       // edge scores
__device__ float g_ex  [EE * 2];       // exp(s - max)
__device__ float g_smax[NN * 2];       // per-dst per-head max
__device__ float g_den [NN * 2];       // per-dst per-head sum

// ---------------- helpers ----------------
__device__ __forceinline__ float lrelu(float v) { return v > 0.f ? v : 0.2f * v; }

__device__ __forceinline__ void atomicMaxF(float* addr, float v) {
    if (v >= 0.f) atomicMax((int*)addr, __float_as_int(v));
    else          atomicMin((unsigned int*)addr, __float_as_uint(v));
}

__device__ __forceinline__ void red4(float* p, float a, float b, float c, float d) {
    asm volatile("red.global.add.v4.f32 [%0], {%1,%2,%3,%4};"
                 :: "l"(p), "f"(a), "f"(b), "f"(c), "f"(d) : "memory");
}

// ---------------- layernorm: warp per row (128 dims = 32 lanes x float4) ----------------
__global__ void ln_kernel(const float* __restrict__ x, const float* __restrict__ g,
                          const float* __restrict__ b, float* __restrict__ out, int n)
{
    int warp = (blockIdx.x * blockDim.x + threadIdx.x) >> 5;
    int lane = threadIdx.x & 31;
    if (warp >= n) return;
    const float4 v = ((const float4*)(x + (size_t)warp * DIM))[lane];
    float s = v.x + v.y + v.z + v.w;
    #pragma unroll
    for (int o = 16; o; o >>= 1) s += __shfl_xor_sync(~0u, s, o);
    float mu = s * (1.f / 128.f);
    float dx = v.x - mu, dy = v.y - mu, dz = v.z - mu, dw = v.w - mu;
    float q = dx*dx + dy*dy + dz*dz + dw*dw;
    #pragma unroll
    for (int o = 16; o; o >>= 1) q += __shfl_xor_sync(~0u, q, o);
    float r = rsqrtf(q * (1.f / 128.f) + 1e-5f);
    float4 gv = ((const float4*)g)[lane];
    float4 bv = ((const float4*)b)[lane];
    float4 o4;
    o4.x = dx * r * gv.x + bv.x;
    o4.y = dy * r * gv.y + bv.y;
    o4.z = dz * r * gv.z + bv.z;
    o4.w = dw * r * gv.w + bv.w;
    ((float4*)(out + (size_t)warp * DIM))[lane] = o4;
}

// ---------------- SGEMM: 64x64x16 tile, 256 threads, 4x4 per thread ----------------
// MODE 0: C = A@B + bias ; MODE 1: C = res + A@B + bias ; MODE 2: C = gelu(A@B + bias)
// abias (optional): added to A columns during load (A[m,k] + abias[k])
template<int MODE>
__global__ void __launch_bounds__(256) sgemm_kernel(
    const float* __restrict__ A, const float* __restrict__ B,
    const float* __restrict__ bias, const float* __restrict__ abias,
    const float* __restrict__ res, float* __restrict__ C,
    int M, int K, int Nc)
{
    __shared__ float As[16][64];
    __shared__ float Bs[16][64];
    int tid = threadIdx.x;
    int tx = tid & 15, ty = tid >> 4;
    int m0 = blockIdx.y * 64, n0 = blockIdx.x * 64;
    int arow = tid >> 2, acol = (tid & 3) * 4;
    int brow = tid >> 4, bcol = (tid & 15) * 4;
    float acc[4][4] = {};
    for (int kt = 0; kt < K; kt += 16) {
        float4 av = make_float4(0.f, 0.f, 0.f, 0.f);
        int gr = m0 + arow;
        if (gr < M) av = *(const float4*)(A + (size_t)gr * K + kt + acol);
        if (abias) {
            av.x += abias[kt + acol + 0];
            av.y += abias[kt + acol + 1];
            av.z += abias[kt + acol + 2];
            av.w += abias[kt + acol + 3];
        }
        As[acol + 0][arow] = av.x;
        As[acol + 1][arow] = av.y;
        As[acol + 2][arow] = av.z;
        As[acol + 3][arow] = av.w;
        float4 bv = *(const float4*)(B + (size_t)(kt + brow) * Nc + n0 + bcol);
        *(float4*)&Bs[brow][bcol] = bv;
        __syncthreads();
        #pragma unroll
        for (int k = 0; k < 16; k++) {
            float a[4], bb[4];
            #pragma unroll
            for (int i = 0; i < 4; i++) a[i]  = As[k][ty * 4 + i];
            #pragma unroll
            for (int j = 0; j < 4; j++) bb[j] = Bs[k][tx * 4 + j];
            #pragma unroll
            for (int i = 0; i < 4; i++)
                #pragma unroll
                for (int j = 0; j < 4; j++)
                    acc[i][j] = fmaf(a[i], bb[j], acc[i][j]);
        }
        __syncthreads();
    }
    #pragma unroll
    for (int i = 0; i < 4; i++) {
        int r = m0 + ty * 4 + i;
        if (r >= M) break;
        #pragma unroll
        for (int j = 0; j < 4; j++) {
            int c = n0 + tx * 4 + j;
            float v = acc[i][j] + bias[c];
            if (MODE == 1) v += res[(size_t)r * Nc + c];
            if (MODE == 2) v = 0.5f * v * (1.f + erff(v * 0.70710678118654752f));
            C[(size_t)r * Nc + c] = v;
        }
    }
}

// ---------------- edge pass A: scores + segment max ----------------
__global__ void edge_score_kernel(const float4* __restrict__ xl, const float4* __restrict__ xr,
                                  const int* __restrict__ src, const int* __restrict__ dst,
                                  const float* __restrict__ att,
                                  float* __restrict__ s, float* __restrict__ smax, int ne)
{
    int e    = (blockIdx.x * blockDim.x + threadIdx.x) >> 5;
    int lane = threadIdx.x & 31;
    if (e >= ne) return;
    int sv = src[e], dv = dst[e];
    const float4* a4 = (const float4*)att;
    float acc0, acc1;
    {
        float4 l4 = xl[(size_t)sv * 64 + lane];
        float4 r4 = xr[(size_t)dv * 64 + lane];
        float4 at = a4[lane];
        acc0 = lrelu(l4.x + r4.x) * at.x + lrelu(l4.y + r4.y) * at.y
             + lrelu(l4.z + r4.z) * at.z + lrelu(l4.w + r4.w) * at.w;
    }
    {
        float4 l4 = xl[(size_t)sv * 64 + 32 + lane];
        float4 r4 = xr[(size_t)dv * 64 + 32 + lane];
        float4 at = a4[32 + lane];
        acc1 = lrelu(l4.x + r4.x) * at.x + lrelu(l4.y + r4.y) * at.y
             + lrelu(l4.z + r4.z) * at.z + lrelu(l4.w + r4.w) * at.w;
    }
    #pragma unroll
    for (int o = 16; o; o >>= 1) {
        acc0 += __shfl_xor_sync(~0u, acc0, o);
        acc1 += __shfl_xor_sync(~0u, acc1, o);
    }
    if (lane == 0) {
        s[e * 2 + 0] = acc0;
        s[e * 2 + 1] = acc1;
        atomicMaxF(smax + dv * 2 + 0, acc0);
        atomicMaxF(smax + dv * 2 + 1, acc1);
    }
}

__global__ void init_smax_kernel(float* __restrict__ smax, int n2)
{
    int i = blockIdx.x * blockDim.x + threadIdx.x;
    if (i < n2) smax[i] = -3.402823466e38f;
}

// ---------------- edge pass B: exp + segment sum ----------------
__global__ void edge_exp_kernel(const float* __restrict__ s, const float* __restrict__ smax,
                                const int* __restrict__ dst,
                                float* __restrict__ ex, float* __restrict__ den, int ne)
{
    int i = blockIdx.x * blockDim.x + threadIdx.x;
    if (i >= 2 * ne) return;
    int e = i >> 1, h = i & 1;
    int d = dst[e];
    float v = expf(s[i] - smax[d * 2 + h]);
    ex[i] = v;
    atomicAdd(den + d * 2 + h, v);
}

// ---------------- edge pass C: weighted aggregate ----------------
__global__ void edge_agg_kernel(const float4* __restrict__ xl,
                                const int* __restrict__ src, const int* __restrict__ dst,
                                const float* __restrict__ ex, const float* __restrict__ den,
                                float* __restrict__ agg, int ne)
{
    int e    = (blockIdx.x * blockDim.x + threadIdx.x) >> 5;
    int lane = threadIdx.x & 31;
    if (e >= ne) return;
    int sv = src[e], dv = dst[e];
    float a0 = ex[e * 2 + 0] / (den[dv * 2 + 0] + 1e-16f);
    float a1 = ex[e * 2 + 1] / (den[dv * 2 + 1] + 1e-16f);
    {
        float4 v = xl[(size_t)sv * 64 + lane];
        red4(agg + (size_t)dv * HC + lane * 4, v.x * a0, v.y * a0, v.z * a0, v.w * a0);
    }
    {
        float4 v = xl[(size_t)sv * 64 + 32 + lane];
        red4(agg + (size_t)dv * HC + 128 + lane * 4, v.x * a1, v.y * a1, v.z * a1, v.w * a1);
    }
}

// ---------------- host ----------------
extern "C" void kernel_launch(void* const* d_in, const int* in_sizes, int n_in,
                              void* d_out, int out_size)
{
    const float* x     = (const float*)d_in[0];
    const int*   ei    = (const int*)  d_in[1];
    const float* ln1_g = (const float*)d_in[2];
    const float* ln1_b = (const float*)d_in[3];
    const float* Wl    = (const float*)d_in[4];
    const float* bl    = (const float*)d_in[5];
    const float* Wr    = (const float*)d_in[6];
    const float* br    = (const float*)d_in[7];
    const float* att   = (const float*)d_in[8];
    const float* gat_b = (const float*)d_in[9];
    const float* Wp    = (const float*)d_in[10];
    const float* bp    = (const float*)d_in[11];
    const float* ln2_g = (const float*)d_in[12];
    const float* ln2_b = (const float*)d_in[13];
    const float* W1    = (const float*)d_in[14];
    const float* b1    = (const float*)d_in[15];
    const float* W2    = (const float*)d_in[16];
    const float* b2    = (const float*)d_in[17];

    const int n  = NN;
    const int ne = EE;
    const int* src = ei;
    const int* dst = ei + ne;

    float *gx, *gh, *gxl, *gxr, *gagg, *gmlp, *gs, *gex, *gsmax, *gden;
    cudaGetSymbolAddress((void**)&gx,   g_x);
    cudaGetSymbolAddress((void**)&gh,   g_h);
    cudaGetSymbolAddress((void**)&gxl,  g_xl);
    cudaGetSymbolAddress((void**)&gxr,  g_xr);
    cudaGetSymbolAddress((void**)&gagg, g_agg);
    cudaGetSymbolAddress((void**)&gmlp, g_mlp);
    cudaGetSymbolAddress((void**)&gs,   g_s);
    cudaGetSymbolAddress((void**)&gex,  g_ex);
    cudaGetSymbolAddress((void**)&gsmax,g_smax);
    cudaGetSymbolAddress((void**)&gden, g_den);

    cudaMemcpyAsync(gx, x, sizeof(float) * (size_t)n * DIM, cudaMemcpyDeviceToDevice);

    const int lnBlocks   = (n + 7) / 8;          // 8 warps / block
    const int edgeBlocks = (ne + 7) / 8;         // warp per edge

    for (int l = 0; l < 2; l++) {
        // --- attention block ---
        ln_kernel<<<lnBlocks, 256>>>(gx, ln1_g + l * DIM, ln1_b + l * DIM, gh, n);

        dim3 gWlr(HC / 64, (n + 63) / 64);
        sgemm_kernel<0><<<gWlr, 256>>>(gh, Wl + (size_t)l * DIM * HC, bl + l * HC,
                                       nullptr, nullptr, gxl, n, DIM, HC);
        sgemm_kernel<0><<<gWlr, 256>>>(gh, Wr + (size_t)l * DIM * HC, br + l * HC,
                                       nullptr, nullptr, gxr, n, DIM, HC);

        cudaMemsetAsync(gagg, 0, sizeof(float) * (size_t)n * HC);
        cudaMemsetAsync(gden, 0, sizeof(float) * (size_t)n * 2);
        init_smax_kernel<<<(2 * n + 255) / 256, 256>>>(gsmax, 2 * n);

        edge_score_kernel<<<edgeBlocks, 256>>>((const float4*)gxl, (const float4*)gxr,
                                               src, dst, att + l * HC, gs, gsmax, ne);
        edge_exp_kernel<<<(2 * ne + 255) / 256, 256>>>(gs, gsmax, dst, gex, gden, ne);
        edge_agg_kernel<<<edgeBlocks, 256>>>((const float4*)gxl, src, dst, gex, gden, gagg, ne);

        dim3 gWp(DIM / 64, (n + 63) / 64);
        sgemm_kernel<1><<<gWp, 256>>>(gagg, Wp + (size_t)l * HC * DIM, bp + l * DIM,
                                      gat_b + l * HC, gx, gx, n, HC, DIM);

        // --- MLP block ---
        ln_kernel<<<lnBlocks, 256>>>(gx, ln2_g + l * DIM, ln2_b + l * DIM, gh, n);

        dim3 gW1(DMLP / 64, (n + 63) / 64);
        sgemm_kernel<2><<<gW1, 256>>>(gh, W1 + (size_t)l * DIM * DMLP, b1 + l * DMLP,
                                      nullptr, nullptr, gmlp, n, DIM, DMLP);

        dim3 gW2(DIM / 64, (n + 63) / 64);
        sgemm_kernel<1><<<gW2, 256>>>(gmlp, W2 + (size_t)l * DMLP * DIM, b2 + l * DIM,
                                      nullptr, gx, gx, n, DMLP, DIM);
    }

    cudaMemcpyAsync(d_out, gx, sizeof(float) * (size_t)n * DIM, cudaMemcpyDeviceToDevice);
}

// round 4
// speedup vs baseline: 1.6901x; 1.6901x over previous
#include <cuda_runtime.h>
#include <cuda_bf16.h>
#include <math.h>
#include <stdint.h>

#define NN 50000
#define EE 800000
#define DIM 128
#define HC 256        // HEADS*DIM
#define DMLP 512

// ---------------- scratch (device globals; no allocation) ----------------
__device__ float g_x   [NN * DIM];
__device__ float g_h   [NN * DIM];
__device__ float g_xl  [NN * HC];
__device__ float g_xr  [NN * HC];
__device__ float g_agg [NN * HC];
__device__ float g_mlp [NN * DMLP];
__device__ float g_s   [EE * 2];
__device__ float g_ex  [EE * 2];
__device__ float g_smax[NN * 2];
__device__ float g_den [NN * 2];
__device__ float g_bpe [DIM];

// ---------------- helpers ----------------
__device__ __forceinline__ float lrelu(float v) { return v > 0.f ? v : 0.2f * v; }

__device__ __forceinline__ void atomicMaxF(float* addr, float v) {
    if (v >= 0.f) atomicMax((int*)addr, __float_as_int(v));
    else          atomicMin((unsigned int*)addr, __float_as_uint(v));
}

__device__ __forceinline__ void red4(float* p, float a, float b, float c, float d) {
    asm volatile("red.global.add.v4.f32 [%0], {%1,%2,%3,%4};"
                 :: "l"(p), "f"(a), "f"(b), "f"(c), "f"(d) : "memory");
}

__device__ __forceinline__ uint32_t smem_u32(const void* p) {
    return (uint32_t)__cvta_generic_to_shared(p);
}

#define CP_ASYNC16(dst, src, szbytes) \
    asm volatile("cp.async.cg.shared.global [%0], [%1], 16, %2;" \
                 :: "r"(dst), "l"(src), "r"(szbytes))
#define CP_COMMIT()  asm volatile("cp.async.commit_group;")
#define CP_WAIT0()   asm volatile("cp.async.wait_group 0;")

// ---------------- layernorm: warp per row ----------------
__global__ void ln_kernel(const float* __restrict__ x, const float* __restrict__ g,
                          const float* __restrict__ b, float* __restrict__ out, int n)
{
    int warp = (blockIdx.x * blockDim.x + threadIdx.x) >> 5;
    int lane = threadIdx.x & 31;
    if (warp >= n) return;
    const float4 v = ((const float4*)(x + (size_t)warp * DIM))[lane];
    float s = v.x + v.y + v.z + v.w;
    #pragma unroll
    for (int o = 16; o; o >>= 1) s += __shfl_xor_sync(~0u, s, o);
    float mu = s * (1.f / 128.f);
    float dx = v.x - mu, dy = v.y - mu, dz = v.z - mu, dw = v.w - mu;
    float q = dx*dx + dy*dy + dz*dz + dw*dw;
    #pragma unroll
    for (int o = 16; o; o >>= 1) q += __shfl_xor_sync(~0u, q, o);
    float r = rsqrtf(q * (1.f / 128.f) + 1e-5f);
    float4 gv = ((const float4*)g)[lane];
    float4 bv = ((const float4*)b)[lane];
    float4 o4;
    o4.x = dx * r * gv.x + bv.x;
    o4.y = dy * r * gv.y + bv.y;
    o4.z = dz * r * gv.z + bv.z;
    o4.w = dw * r * gv.w + bv.w;
    ((float4*)(out + (size_t)warp * DIM))[lane] = o4;
}

// ---------------- TF32 tensor-core GEMM ----------------
// 128x128 block tile, BK=16, 256 threads = 8 warps (2x4), warp tile 64x32.
// MODE 0: C = A@B + bias ; MODE 1: C = res + A@B + bias ; MODE 2: C = gelu(A@B + bias)
#define ASTR 20    // A smem row stride (floats), conflict-free
#define BSTR 136   // B smem row stride (floats), conflict-free

template<int MODE>
__global__ void __launch_bounds__(256) tgemm_kernel(
    const float* __restrict__ A, const float* __restrict__ B,
    const float* __restrict__ bias, const float* __restrict__ res,
    float* __restrict__ C, int M, int K, int Nc)
{
    __shared__ float As[2][128 * ASTR];
    __shared__ float Bs[2][16 * BSTR];

    const int tid  = threadIdx.x;
    const int lane = tid & 31;
    const int wid  = tid >> 5;
    const int wr   = wid >> 2;          // 0..1 : warp row (64 rows)
    const int wc   = wid & 3;           // 0..3 : warp col (32 cols)
    const int m0   = blockIdx.y * 128;
    const int n0   = blockIdx.x * 128;

    const int fA0 = tid * 2;
    const int fB0 = tid * 2;

    float acc[4][4][4];
    #pragma unroll
    for (int i = 0; i < 4; i++)
        #pragma unroll
        for (int j = 0; j < 4; j++)
            #pragma unroll
            for (int k = 0; k < 4; k++) acc[i][j][k] = 0.f;

    const int NK = K >> 4;

    auto load_stage = [&](int buf, int kt) {
        #pragma unroll
        for (int i = 0; i < 2; i++) {
            int f   = fA0 + i;             // 0..511
            int row = f >> 2;
            int k4  = (f & 3) * 4;
            bool ok = (m0 + row) < M;
            const float* src = A + (size_t)(ok ? (m0 + row) : 0) * K + kt * 16 + k4;
            uint32_t dst = smem_u32(&As[buf][row * ASTR + k4]);
            CP_ASYNC16(dst, src, ok ? 16 : 0);
        }
        #pragma unroll
        for (int i = 0; i < 2; i++) {
            int f   = fB0 + i;             // 0..511
            int row = f >> 5;
            int n4  = (f & 31) * 4;
            const float* src = B + (size_t)(kt * 16 + row) * Nc + n0 + n4;
            uint32_t dst = smem_u32(&Bs[buf][row * BSTR + n4]);
            CP_ASYNC16(dst, src, 16);
        }
        CP_COMMIT();
    };

    load_stage(0, 0);
    int buf = 0;

    for (int kt = 0; kt < NK; kt++) {
        CP_WAIT0();
        __syncthreads();
        if (kt + 1 < NK) load_stage(buf ^ 1, kt + 1);

        #pragma unroll
        for (int ks = 0; ks < 2; ks++) {
            const int kk = ks * 8;
            uint32_t a[4][4], b[4][2];
            #pragma unroll
            for (int mt = 0; mt < 4; mt++) {
                const float* Ab = &As[buf][(wr * 64 + mt * 16 + (lane >> 2)) * ASTR + kk + (lane & 3)];
                a[mt][0] = __float_as_uint(Ab[0]);
                a[mt][1] = __float_as_uint(Ab[8 * ASTR]);
                a[mt][2] = __float_as_uint(Ab[4]);
                a[mt][3] = __float_as_uint(Ab[8 * ASTR + 4]);
            }
            #pragma unroll
            for (int nt = 0; nt < 4; nt++) {
                const float* Bb = &Bs[buf][(kk + (lane & 3)) * BSTR + wc * 32 + nt * 8 + (lane >> 2)];
                b[nt][0] = __float_as_uint(Bb[0]);
                b[nt][1] = __float_as_uint(Bb[4 * BSTR]);
            }
            #pragma unroll
            for (int mt = 0; mt < 4; mt++)
                #pragma unroll
                for (int nt = 0; nt < 4; nt++) {
                    asm volatile(
                        "mma.sync.aligned.m16n8k8.row.col.f32.tf32.tf32.f32 "
                        "{%0,%1,%2,%3},{%4,%5,%6,%7},{%8,%9},{%0,%1,%2,%3};"
                        : "+f"(acc[mt][nt][0]), "+f"(acc[mt][nt][1]),
                          "+f"(acc[mt][nt][2]), "+f"(acc[mt][nt][3])
                        : "r"(a[mt][0]), "r"(a[mt][1]), "r"(a[mt][2]), "r"(a[mt][3]),
                          "r"(b[nt][0]), "r"(b[nt][1]));
                }
        }
        buf ^= 1;
    }

    // epilogue
    #pragma unroll
    for (int mt = 0; mt < 4; mt++) {
        #pragma unroll
        for (int nt = 0; nt < 4; nt++) {
            int r0 = m0 + wr * 64 + mt * 16 + (lane >> 2);
            int c  = n0 + wc * 32 + nt * 8 + (lane & 3) * 2;
            float bx = bias[c], by = bias[c + 1];
            #pragma unroll
            for (int half = 0; half < 2; half++) {
                int r = r0 + half * 8;
                if (r >= M) continue;
                float vx = acc[mt][nt][half * 2 + 0] + bx;
                float vy = acc[mt][nt][half * 2 + 1] + by;
                if (MODE == 1) {
                    const float2 rv = *(const float2*)(res + (size_t)r * Nc + c);
                    vx += rv.x; vy += rv.y;
                }
                if (MODE == 2) {
                    vx = 0.5f * vx * (1.f + erff(vx * 0.70710678118654752f));
                    vy = 0.5f * vy * (1.f + erff(vy * 0.70710678118654752f));
                }
                *(float2*)(C + (size_t)r * Nc + c) = make_float2(vx, vy);
            }
        }
    }
}

// ---------------- effective bias for Wp: bpe = bp + gat_b @ Wp ----------------
__global__ void bpe_kernel(const float* __restrict__ gat_b, const float* __restrict__ Wp,
                           const float* __restrict__ bp, float* __restrict__ out)
{
    int j = threadIdx.x;   // 128
    float s = bp[j];
    #pragma unroll 8
    for (int i = 0; i < HC; i++) s += gat_b[i] * Wp[(size_t)i * DIM + j];
    out[j] = s;
}

// ---------------- edge pass A: scores + segment max ----------------
__global__ void edge_score_kernel(const float4* __restrict__ xl, const float4* __restrict__ xr,
                                  const int* __restrict__ src, const int* __restrict__ dst,
                                  const float* __restrict__ att,
                                  float* __restrict__ s, float* __restrict__ smax, int ne)
{
    int e    = (blockIdx.x * blockDim.x + threadIdx.x) >> 5;
    int lane = threadIdx.x & 31;
    if (e >= ne) return;
    int sv = src[e], dv = dst[e];
    const float4* a4 = (const float4*)att;
    float acc0, acc1;
    {
        float4 l4 = xl[(size_t)sv * 64 + lane];
        float4 r4 = xr[(size_t)dv * 64 + lane];
        float4 at = a4[lane];
        acc0 = lrelu(l4.x + r4.x) * at.x + lrelu(l4.y + r4.y) * at.y
             + lrelu(l4.z + r4.z) * at.z + lrelu(l4.w + r4.w) * at.w;
    }
    {
        float4 l4 = xl[(size_t)sv * 64 + 32 + lane];
        float4 r4 = xr[(size_t)dv * 64 + 32 + lane];
        float4 at = a4[32 + lane];
        acc1 = lrelu(l4.x + r4.x) * at.x + lrelu(l4.y + r4.y) * at.y
             + lrelu(l4.z + r4.z) * at.z + lrelu(l4.w + r4.w) * at.w;
    }
    #pragma unroll
    for (int o = 16; o; o >>= 1) {
        acc0 += __shfl_xor_sync(~0u, acc0, o);
        acc1 += __shfl_xor_sync(~0u, acc1, o);
    }
    if (lane == 0) {
        s[e * 2 + 0] = acc0;
        s[e * 2 + 1] = acc1;
        atomicMaxF(smax + dv * 2 + 0, acc0);
        atomicMaxF(smax + dv * 2 + 1, acc1);
    }
}

__global__ void init_smax_kernel(float* __restrict__ smax, int n2)
{
    int i = blockIdx.x * blockDim.x + threadIdx.x;
    if (i < n2) smax[i] = -3.402823466e38f;
}

// ---------------- edge pass B: exp + segment sum ----------------
__global__ void edge_exp_kernel(const float* __restrict__ s, const float* __restrict__ smax,
                                const int* __restrict__ dst,
                                float* __restrict__ ex, float* __restrict__ den, int ne)
{
    int i = blockIdx.x * blockDim.x + threadIdx.x;
    if (i >= 2 * ne) return;
    int e = i >> 1, h = i & 1;
    int d = dst[e];
    float v = expf(s[i] - smax[d * 2 + h]);
    ex[i] = v;
    atomicAdd(den + d * 2 + h, v);
}

// ---------------- edge pass C: weighted aggregate ----------------
__global__ void edge_agg_kernel(const float4* __restrict__ xl,
                                const int* __restrict__ src, const int* __restrict__ dst,
                                const float* __restrict__ ex, const float* __restrict__ den,
                                float* __restrict__ agg, int ne)
{
    int e    = (blockIdx.x * blockDim.x + threadIdx.x) >> 5;
    int lane = threadIdx.x & 31;
    if (e >= ne) return;
    int sv = src[e], dv = dst[e];
    float a0 = ex[e * 2 + 0] / (den[dv * 2 + 0] + 1e-16f);
    float a1 = ex[e * 2 + 1] / (den[dv * 2 + 1] + 1e-16f);
    {
        float4 v = xl[(size_t)sv * 64 + lane];
        red4(agg + (size_t)dv * HC + lane * 4, v.x * a0, v.y * a0, v.z * a0, v.w * a0);
    }
    {
        float4 v = xl[(size_t)sv * 64 + 32 + lane];
        red4(agg + (size_t)dv * HC + 128 + lane * 4, v.x * a1, v.y * a1, v.z * a1, v.w * a1);
    }
}

// ---------------- host ----------------
extern "C" void kernel_launch(void* const* d_in, const int* in_sizes, int n_in,
                              void* d_out, int out_size)
{
    const float* x     = (const float*)d_in[0];
    const int*   ei    = (const int*)  d_in[1];
    const float* ln1_g = (const float*)d_in[2];
    const float* ln1_b = (const float*)d_in[3];
    const float* Wl    = (const float*)d_in[4];
    const float* bl    = (const float*)d_in[5];
    const float* Wr    = (const float*)d_in[6];
    const float* br    = (const float*)d_in[7];
    const float* att   = (const float*)d_in[8];
    const float* gat_b = (const float*)d_in[9];
    const float* Wp    = (const float*)d_in[10];
    const float* bp    = (const float*)d_in[11];
    const float* ln2_g = (const float*)d_in[12];
    const float* ln2_b = (const float*)d_in[13];
    const float* W1    = (const float*)d_in[14];
    const float* b1    = (const float*)d_in[15];
    const float* W2    = (const float*)d_in[16];
    const float* b2    = (const float*)d_in[17];

    const int n  = NN;
    const int ne = EE;
    const int* src = ei;
    const int* dst = ei + ne;

    float *gx, *gh, *gxl, *gxr, *gagg, *gmlp, *gs, *gex, *gsmax, *gden, *gbpe;
    cudaGetSymbolAddress((void**)&gx,   g_x);
    cudaGetSymbolAddress((void**)&gh,   g_h);
    cudaGetSymbolAddress((void**)&gxl,  g_xl);
    cudaGetSymbolAddress((void**)&gxr,  g_xr);
    cudaGetSymbolAddress((void**)&gagg, g_agg);
    cudaGetSymbolAddress((void**)&gmlp, g_mlp);
    cudaGetSymbolAddress((void**)&gs,   g_s);
    cudaGetSymbolAddress((void**)&gex,  g_ex);
    cudaGetSymbolAddress((void**)&gsmax,g_smax);
    cudaGetSymbolAddress((void**)&gden, g_den);
    cudaGetSymbolAddress((void**)&gbpe, g_bpe);

    cudaMemcpyAsync(gx, x, sizeof(float) * (size_t)n * DIM, cudaMemcpyDeviceToDevice);

    const int lnBlocks   = (n + 7) / 8;
    const int edgeBlocks = (ne + 7) / 8;
    const int mBlocks    = (n + 127) / 128;   // 391

    for (int l = 0; l < 2; l++) {
        // --- attention block ---
        ln_kernel<<<lnBlocks, 256>>>(gx, ln1_g + l * DIM, ln1_b + l * DIM, gh, n);

        tgemm_kernel<0><<<dim3(HC / 128, mBlocks), 256>>>(
            gh, Wl + (size_t)l * DIM * HC, bl + l * HC, nullptr, gxl, n, DIM, HC);
        tgemm_kernel<0><<<dim3(HC / 128, mBlocks), 256>>>(
            gh, Wr + (size_t)l * DIM * HC, br + l * HC, nullptr, gxr, n, DIM, HC);

        cudaMemsetAsync(gagg, 0, sizeof(float) * (size_t)n * HC);
        cudaMemsetAsync(gden, 0, sizeof(float) * (size_t)n * 2);
        init_smax_kernel<<<(2 * n + 255) / 256, 256>>>(gsmax, 2 * n);

        edge_score_kernel<<<edgeBlocks, 256>>>((const float4*)gxl, (const float4*)gxr,
                                               src, dst, att + l * HC, gs, gsmax, ne);
        edge_exp_kernel<<<(2 * ne + 255) / 256, 256>>>(gs, gsmax, dst, gex, gden, ne);
        edge_agg_kernel<<<edgeBlocks, 256>>>((const float4*)gxl, src, dst, gex, gden, gagg, ne);

        bpe_kernel<<<1, DIM>>>(gat_b + l * HC, Wp + (size_t)l * HC * DIM, bp + l * DIM, gbpe);
        tgemm_kernel<1><<<dim3(DIM / 128, mBlocks), 256>>>(
            gagg, Wp + (size_t)l * HC * DIM, gbpe, gx, gx, n, HC, DIM);

        // --- MLP block ---
        ln_kernel<<<lnBlocks, 256>>>(gx, ln2_g + l * DIM, ln2_b + l * DIM, gh, n);

        tgemm_kernel<2><<<dim3(DMLP / 128, mBlocks), 256>>>(
            gh, W1 + (size_t)l * DIM * DMLP, b1 + l * DMLP, nullptr, gmlp, n, DIM, DMLP);

        tgemm_kernel<1><<<dim3(DIM / 128, mBlocks), 256>>>(
            gmlp, W2 + (size_t)l * DMLP * DIM, b2 + l * DIM, gx, gx, n, DMLP, DIM);
    }

    cudaMemcpyAsync(d_out, gx, sizeof(float) * (size_t)n * DIM, cudaMemcpyDeviceToDevice);
}